// round 16
// baseline (speedup 1.0000x reference)
#include <cuda_runtime.h>
#include <cuda_fp16.h>
#include <math.h>

#define B_  2
#define S_  4096
#define D_  384
#define H_  6
#define DK  64
#define R_  (B_*S_)
#define EPS 1e-6f
#define LDS 72    // smem row stride (fp16 elems): 144B rows -> conflict-free ldmatrix
#define NT  (S_/64)

// ---------------- scratch (device globals; no allocation allowed) ----------
__device__ __half g_zh[R_ * D_];                 // double-LN output (fp16)
__device__ __half g_q[B_ * H_ * S_ * DK];        // pre-scaled by 0.125*log2(e)
__device__ __half g_k[B_ * H_ * S_ * DK];
__device__ __half g_v[B_ * H_ * S_ * DK];
__device__ __half g_oh[R_ * D_];                 // attention output (fp16)
__device__ __half g_wh[4 * D_ * D_];             // wq|wk|wv|wo in fp16

// ---------------- mma / ldmatrix helpers ------------------------------------
__device__ __forceinline__ unsigned smem_u32(const void* p) {
    return (unsigned)__cvta_generic_to_shared(p);
}
__device__ __forceinline__ void ldm_x4(unsigned r[4], const void* p) {
    unsigned a = smem_u32(p);
    asm volatile("ldmatrix.sync.aligned.m8n8.x4.shared.b16 {%0,%1,%2,%3}, [%4];"
                 : "=r"(r[0]), "=r"(r[1]), "=r"(r[2]), "=r"(r[3]) : "r"(a));
}
__device__ __forceinline__ void ldm_x4_t(unsigned r[4], const void* p) {
    unsigned a = smem_u32(p);
    asm volatile("ldmatrix.sync.aligned.m8n8.x4.trans.shared.b16 {%0,%1,%2,%3}, [%4];"
                 : "=r"(r[0]), "=r"(r[1]), "=r"(r[2]), "=r"(r[3]) : "r"(a));
}
// fp32-accumulator mma
__device__ __forceinline__ void mma_f16(float c[4], const unsigned a[4],
                                        unsigned b0, unsigned b1) {
    asm volatile("mma.sync.aligned.m16n8k16.row.col.f32.f16.f16.f32 "
                 "{%0,%1,%2,%3}, {%4,%5,%6,%7}, {%8,%9}, {%0,%1,%2,%3};"
                 : "+f"(c[0]), "+f"(c[1]), "+f"(c[2]), "+f"(c[3])
                 : "r"(a[0]), "r"(a[1]), "r"(a[2]), "r"(a[3]), "r"(b0), "r"(b1));
}
// fp16-accumulator mma (accumulating form)
__device__ __forceinline__ void mma_f16c16(unsigned c[2], const unsigned a[4],
                                           unsigned b0, unsigned b1) {
    asm volatile("mma.sync.aligned.m16n8k16.row.col.f16.f16.f16.f16 "
                 "{%0,%1}, {%2,%3,%4,%5}, {%6,%7}, {%0,%1};"
                 : "+r"(c[0]), "+r"(c[1])
                 : "r"(a[0]), "r"(a[1]), "r"(a[2]), "r"(a[3]), "r"(b0), "r"(b1));
}
// fp16-accumulator mma, zero-initializing (C = 0)
__device__ __forceinline__ void mma_f16c16_z(unsigned c[2], const unsigned a[4],
                                             unsigned b0, unsigned b1) {
    asm volatile("mma.sync.aligned.m16n8k16.row.col.f16.f16.f16.f16 "
                 "{%0,%1}, {%2,%3,%4,%5}, {%6,%7}, {%8,%8};"
                 : "=r"(c[0]), "=r"(c[1])
                 : "r"(a[0]), "r"(a[1]), "r"(a[2]), "r"(a[3]), "r"(b0), "r"(b1),
                   "r"(0u));
}
// pack two f32 into f16x2: low half = lo, high half = hi
__device__ __forceinline__ unsigned pack_f16(float lo, float hi) {
    unsigned d;
    asm("cvt.rn.f16x2.f32 %0, %1, %2;" : "=r"(d) : "f"(hi), "f"(lo));
    return d;
}
// two exponentials (base 2) in one op; in-place on an fp16x2 fragment reg
__device__ __forceinline__ unsigned ex2_h2(unsigned x) {
    unsigned r;
    asm("ex2.approx.f16x2 %0, %1;" : "=r"(r) : "r"(x));
    return r;
}
__device__ __forceinline__ unsigned hadd2(unsigned a, unsigned b) {
    unsigned d;
    asm("add.f16x2 %0, %1, %2;" : "=r"(d) : "r"(a), "r"(b));
    return d;
}
__device__ __forceinline__ void cp_async16(void* dst, const void* src) {
    unsigned d = smem_u32(dst);
    asm volatile("cp.async.cg.shared.global [%0], [%1], 16;" :: "r"(d), "l"(src));
}
#define CP_COMMIT() asm volatile("cp.async.commit_group;" ::: "memory")
#define CP_WAIT0()  asm volatile("cp.async.wait_group 0;" ::: "memory")
#define CP_WAIT1()  asm volatile("cp.async.wait_group 1;" ::: "memory")

// ---------------- weight conversion ------------------------------------------
__global__ __launch_bounds__(256) void convw_kernel(
    const float* __restrict__ wq, const float* __restrict__ wk,
    const float* __restrict__ wv, const float* __restrict__ wo)
{
    const float* src = (blockIdx.y == 0) ? wq : (blockIdx.y == 1) ? wk
                     : (blockIdx.y == 2) ? wv : wo;
    __half* dst = g_wh + (size_t)blockIdx.y * D_ * D_;
    int i = (blockIdx.x * 256 + threadIdx.x) * 4;
    float4 v = *(const float4*)(src + i);
    *(unsigned*)(dst + i)     = pack_f16(v.x, v.y);
    *(unsigned*)(dst + i + 2) = pack_f16(v.z, v.w);
}

// ---------------- block reduction (128 threads) ------------------------------
__device__ __forceinline__ float blockSum(float v, float* sh) {
    int tid = threadIdx.x;
#pragma unroll
    for (int o = 16; o > 0; o >>= 1) v += __shfl_xor_sync(0xffffffffu, v, o);
    __syncthreads();
    if ((tid & 31) == 0) sh[tid >> 5] = v;
    __syncthreads();
    return sh[0] + sh[1] + sh[2] + sh[3];
}

// ---------------- fused double LayerNorm (fp32 in, fp16 out) ------------------
__global__ __launch_bounds__(128) void ln2_kernel(
    const float* __restrict__ x,
    const float* __restrict__ ra, const float* __restrict__ rb,
    const float* __restrict__ a0, const float* __restrict__ b0)
{
    __shared__ float sh[4];
    int row = blockIdx.x;
    int tid = threadIdx.x;
    const float* xr = x + (size_t)row * D_;

    float v[3];
#pragma unroll
    for (int c = 0; c < 3; c++) v[c] = xr[tid + 128 * c];

    float s = blockSum(v[0] + v[1] + v[2], sh);
    float mean = s * (1.0f / D_);
    float sq = 0.f;
#pragma unroll
    for (int c = 0; c < 3; c++) { float d = v[c] - mean; sq += d * d; }
    sq = blockSum(sq, sh);
    float inv = 1.0f / (sqrtf(sq * (1.0f / (D_ - 1))) + EPS);

    float y[3];
#pragma unroll
    for (int c = 0; c < 3; c++) {
        int i = tid + 128 * c;
        y[c] = ra[i] * (v[c] - mean) * inv + rb[i];
    }

    s = blockSum(y[0] + y[1] + y[2], sh);
    mean = s * (1.0f / D_);
    sq = 0.f;
#pragma unroll
    for (int c = 0; c < 3; c++) { float d = y[c] - mean; sq += d * d; }
    sq = blockSum(sq, sh);
    inv = 1.0f / (sqrtf(sq * (1.0f / (D_ - 1))) + EPS);

    __half* zr = g_zh + (size_t)row * D_;
#pragma unroll
    for (int c = 0; c < 3; c++) {
        int i = tid + 128 * c;
        zr[i] = __float2half_rn(a0[i] * (y[c] - mean) * inv + b0[i]);
    }
}

// ---------------- projection kernels: cp.async 3-stage ring --------------------
#define PST ((128 + 64) * LDS)            // halfs per stage
#define PROJ_SMEM_BYTES (PST * 3 * 2)     // 82944 bytes -> 2 CTAs/SM, 16 warps

// ---------------- QKV projection (fp16 tensor mma) ----------------------------
// grid (R_/128, 18), 256 threads. Tile 128M x 64N, BK=64.
__global__ __launch_bounds__(256) void mma_qkv_kernel(
    const float* __restrict__ bq, const float* __restrict__ bk,
    const float* __restrict__ bv)
{
    extern __shared__ __half smp[];

    int tid = threadIdx.x, warp = tid >> 5, lane = tid & 31;
    int g = lane >> 2, tig = lane & 3;
    int m0 = blockIdx.x * 128;
    int ntile = blockIdx.y;              // 0..17
    int which = ntile / 6;
    int h = ntile - which * 6;
    const __half* W = g_wh + (size_t)which * (D_ * D_) + (size_t)h * 64 * D_;
    const float* bias = ((which == 0) ? bq : (which == 1) ? bk : bv) + h * 64;
    __half* Out = (which == 0) ? g_q : (which == 1) ? g_k : g_v;

    int r8 = tid >> 3, c8 = tid & 7;

#define QKV_ISSUE(kc) do {                                                      \
        __half* SA_ = smp + ((kc) % 3) * PST;                                   \
        __half* SB_ = SA_ + 128 * LDS;                                          \
        int k0_ = (kc) * 64;                                                    \
        _Pragma("unroll")                                                       \
        for (int j = 0; j < 4; j++) {                                           \
            int r = r8 + j * 32;                                                \
            cp_async16(&SA_[r * LDS + c8 * 8],                                  \
                       g_zh + (size_t)(m0 + r) * D_ + k0_ + c8 * 8);            \
        }                                                                       \
        _Pragma("unroll")                                                       \
        for (int j = 0; j < 2; j++) {                                           \
            int r = r8 + j * 32;                                                \
            cp_async16(&SB_[r * LDS + c8 * 8],                                  \
                       W + (size_t)r * D_ + k0_ + c8 * 8);                      \
        }                                                                       \
        CP_COMMIT();                                                            \
    } while (0)

    QKV_ISSUE(0);
    QKV_ISSUE(1);

    float acc[2][4][4] = {};
    int arow_sel = ((lane & 8) ? 8 : 0) + (lane & 7);
    int acol_sel = ((lane & 16) ? 8 : 0);
    int brow_sel = ((lane & 16) ? 8 : 0) + (lane & 7);
    int bcol_sel = ((lane & 8) ? 8 : 0);
    int mbase = (warp >> 1) * 32;
    int nbase = (warp & 1) * 32;

    for (int kc = 0; kc < 6; kc++) {
        CP_WAIT1();
        __syncthreads();           // chunk kc landed for ALL threads; slot (kc+2)%3 free
        if (kc + 2 < 6) QKV_ISSUE(kc + 2); else CP_COMMIT();

        const __half* SA = smp + (kc % 3) * PST;
        const __half* SB = SA + 128 * LDS;
#pragma unroll
        for (int ks = 0; ks < 4; ks++) {
            unsigned af[2][4], bf0[4], bf1[4];
            ldm_x4(af[0], &SA[(mbase + arow_sel) * LDS + ks * 16 + acol_sel]);
            ldm_x4(af[1], &SA[(mbase + 16 + arow_sel) * LDS + ks * 16 + acol_sel]);
            ldm_x4(bf0, &SB[(nbase + brow_sel) * LDS + ks * 16 + bcol_sel]);
            ldm_x4(bf1, &SB[(nbase + 16 + brow_sel) * LDS + ks * 16 + bcol_sel]);
#pragma unroll
            for (int mi = 0; mi < 2; mi++) {
                mma_f16(acc[mi][0], af[mi], bf0[0], bf0[1]);
                mma_f16(acc[mi][1], af[mi], bf0[2], bf0[3]);
                mma_f16(acc[mi][2], af[mi], bf1[0], bf1[1]);
                mma_f16(acc[mi][3], af[mi], bf1[2], bf1[3]);
            }
        }
    }
#undef QKV_ISSUE

    // fold 1/sqrt(dk) AND log2(e) into q so flash can use raw ex2
    float qs = (which == 0) ? 0.125f * 1.44269504f : 1.0f;
#pragma unroll
    for (int nb = 0; nb < 4; nb++) {
        int j = nbase + nb * 8 + 2 * tig;
        float b0v = bias[j], b1v = bias[j + 1];
#pragma unroll
        for (int mi = 0; mi < 2; mi++) {
            int row = m0 + mbase + mi * 16 + g;
            int bidx = row >> 12;
            int s = row & (S_ - 1);
            __half* po = Out + (((size_t)(bidx * H_ + h)) * S_ + s) * DK + j;
            *(unsigned*)po            = pack_f16((acc[mi][nb][0] + b0v) * qs,
                                                 (acc[mi][nb][1] + b1v) * qs);
            *(unsigned*)(po + 8 * DK) = pack_f16((acc[mi][nb][2] + b0v) * qs,
                                                 (acc[mi][nb][3] + b1v) * qs);
        }
    }
}

// ---------------- output projection + residual (fp16 mma, fp32 out) -----------
__global__ __launch_bounds__(256) void mma_out_kernel(
    const float* __restrict__ bo, const float* __restrict__ xres,
    float* __restrict__ out)
{
    extern __shared__ __half smp[];

    int tid = threadIdx.x, warp = tid >> 5, lane = tid & 31;
    int g = lane >> 2, tig = lane & 3;
    int m0 = blockIdx.x * 128;
    int n0 = blockIdx.y * 64;
    const __half* W = g_wh + (size_t)3 * D_ * D_ + (size_t)n0 * D_;

    int r8 = tid >> 3, c8 = tid & 7;

#define OUT_ISSUE(kc) do {                                                      \
        __half* SA_ = smp + ((kc) % 3) * PST;                                   \
        __half* SB_ = SA_ + 128 * LDS;                                          \
        int k0_ = (kc) * 64;                                                    \
        _Pragma("unroll")                                                       \
        for (int j = 0; j < 4; j++) {                                           \
            int r = r8 + j * 32;                                                \
            cp_async16(&SA_[r * LDS + c8 * 8],                                  \
                       g_oh + (size_t)(m0 + r) * D_ + k0_ + c8 * 8);            \
        }                                                                       \
        _Pragma("unroll")                                                       \
        for (int j = 0; j < 2; j++) {                                           \
            int r = r8 + j * 32;                                                \
            cp_async16(&SB_[r * LDS + c8 * 8],                                  \
                       W + (size_t)r * D_ + k0_ + c8 * 8);                      \
        }                                                                       \
        CP_COMMIT();                                                            \
    } while (0)

    OUT_ISSUE(0);
    OUT_ISSUE(1);

    float acc[2][4][4] = {};
    int arow_sel = ((lane & 8) ? 8 : 0) + (lane & 7);
    int acol_sel = ((lane & 16) ? 8 : 0);
    int brow_sel = ((lane & 16) ? 8 : 0) + (lane & 7);
    int bcol_sel = ((lane & 8) ? 8 : 0);
    int mbase = (warp >> 1) * 32;
    int nbase = (warp & 1) * 32;

    for (int kc = 0; kc < 6; kc++) {
        CP_WAIT1();
        __syncthreads();
        if (kc + 2 < 6) OUT_ISSUE(kc + 2); else CP_COMMIT();

        const __half* SA = smp + (kc % 3) * PST;
        const __half* SB = SA + 128 * LDS;
#pragma unroll
        for (int ks = 0; ks < 4; ks++) {
            unsigned af[2][4], bf0[4], bf1[4];
            ldm_x4(af[0], &SA[(mbase + arow_sel) * LDS + ks * 16 + acol_sel]);
            ldm_x4(af[1], &SA[(mbase + 16 + arow_sel) * LDS + ks * 16 + acol_sel]);
            ldm_x4(bf0, &SB[(nbase + brow_sel) * LDS + ks * 16 + bcol_sel]);
            ldm_x4(bf1, &SB[(nbase + 16 + brow_sel) * LDS + ks * 16 + bcol_sel]);
#pragma unroll
            for (int mi = 0; mi < 2; mi++) {
                mma_f16(acc[mi][0], af[mi], bf0[0], bf0[1]);
                mma_f16(acc[mi][1], af[mi], bf0[2], bf0[3]);
                mma_f16(acc[mi][2], af[mi], bf1[0], bf1[1]);
                mma_f16(acc[mi][3], af[mi], bf1[2], bf1[3]);
            }
        }
    }
#undef OUT_ISSUE

#pragma unroll
    for (int nb = 0; nb < 4; nb++) {
        int col = n0 + nbase + nb * 8 + 2 * tig;
        float b0v = bo[col], b1v = bo[col + 1];
#pragma unroll
        for (int mi = 0; mi < 2; mi++) {
            int row = m0 + mbase + mi * 16 + g;
            float2 x0 = *(const float2*)(xres + (size_t)row * D_ + col);
            float2 x1 = *(const float2*)(xres + (size_t)(row + 8) * D_ + col);
            float2 o0, o1;
            o0.x = x0.x + acc[mi][nb][0] + b0v;
            o0.y = x0.y + acc[mi][nb][1] + b1v;
            o1.x = x1.x + acc[mi][nb][2] + b0v;
            o1.y = x1.y + acc[mi][nb][3] + b1v;
            *(float2*)(out + (size_t)row * D_ + col)       = o0;
            *(float2*)(out + (size_t)(row + 8) * D_ + col) = o1;
        }
    }
}

// ---------------- flash attention (fp16 mma, fixed-base softmax) ---------------
// grid (S_/128, B_*H_), 128 threads (4 warps), 3 CTAs/SM.
// DOUBLE-TILE iterations on a 4-slot K/V ring: ONE wait_group(0) + ONE
// __syncthreads per TWO key-tiles (barriers 64 -> 32 per job). The Q staging
// area is recycled as ring slot 3 after the Q fragments move to registers
// (total smem 4 x 18.4KB = 72KB, still 3 CTAs/SM). Loads issued one full
// 2-tile iteration ahead (~7600 cyc of compute cover ~600 cyc latency).
// Math identical to R14/R15: fp16 S-acc, in-place ex2, hadd2-fused single
// ONES-mma denominator, fp32 O accumulators.
#define STG (128 * LDS)                       // halfs per ring slot (64 K + 64 V rows)
#define FL4_SMEM_BYTES (4 * STG * 2)          // 73728 bytes

__global__ __launch_bounds__(128, 3) void flash_mma_kernel()
{
    extern __shared__ __half smf[];

    int tid = threadIdx.x, warp = tid >> 5, lane = tid & 31;
    int g = lane >> 2, tig = lane & 3;
    int bh = blockIdx.y, qb = blockIdx.x;

    const __half* Qg = g_q + ((size_t)bh * S_ + qb * 128) * DK;
    const __half* Kg = g_k + (size_t)bh * S_ * DK;
    const __half* Vg = g_v + (size_t)bh * S_ * DK;

    int krow = tid >> 3, kchk = tid & 7;     // ring-copy coords (16 rows/pass)

#define FL_ISSUE(t) do {                                                        \
        __half* Kd_ = smf + ((t) & 3) * STG;                                    \
        __half* Vd_ = Kd_ + 64 * LDS;                                           \
        const __half* Kt_ = Kg + (size_t)(t) * 64 * DK;                         \
        const __half* Vt_ = Vg + (size_t)(t) * 64 * DK;                         \
        _Pragma("unroll")                                                       \
        for (int j = 0; j < 4; j++) {                                           \
            int r = krow + j * 16;                                              \
            cp_async16(&Kd_[r * LDS + kchk * 8], Kt_ + r * DK + kchk * 8);      \
            cp_async16(&Vd_[r * LDS + kchk * 8], Vt_ + r * DK + kchk * 8);      \
        }                                                                       \
        CP_COMMIT();                                                            \
    } while (0)

    // prefetch tiles 0,1 into slots 0,1
    FL_ISSUE(0);
    FL_ISSUE(1);

    // Q tile -> slot 3 region (plain loads), then register fragments
    __half* Qs = smf + 3 * STG;
#pragma unroll
    for (int j = 0; j < 8; j++) {
        int i = tid + j * 128;
        int r = i >> 3, c = i & 7;
        *(uint4*)&Qs[r * LDS + c * 8] = *(const uint4*)(Qg + r * DK + c * 8);
    }
    __syncthreads();

    unsigned qf[2][4][4];
    {
        int rsel = ((lane & 8) ? 8 : 0) + (lane & 7);
        int csel = ((lane & 16) ? 8 : 0);
#pragma unroll
        for (int mi = 0; mi < 2; mi++)
#pragma unroll
            for (int kd = 0; kd < 4; kd++)
                ldm_x4(qf[mi][kd], &Qs[(warp * 32 + mi * 16 + rsel) * LDS + kd * 16 + csel]);
    }
    // NOTE: slot 3 (Q area) is first overwritten by FL_ISSUE(3) inside the
    // loop, which happens strictly after the loop-top __syncthreads of ii=0 —
    // that barrier orders every warp's qf ldmatrix reads before the overwrite.

    float fo[2][8][4] = {};
    float lsum[2][4] = {};
    const unsigned ONES = 0x3C003C00u;   // fp16x2 {1.0, 1.0}

    int krow_sel = ((lane & 16) ? 8 : 0) + (lane & 7);   // B-frag (K, non-trans)
    int kcol_sel = ((lane & 8) ? 8 : 0);
    int vrow_sel = ((lane & 8) ? 8 : 0) + (lane & 7);    // B-frag (V, trans)
    int vcol_sel = ((lane & 16) ? 8 : 0);

    for (int ii = 0; ii < NT / 2; ii++) {
        int kt0 = 2 * ii;
        CP_WAIT0();                 // tiles kt0, kt0+1 landed (issued a full iter ago)
        __syncthreads();            // visible to all; prior iteration's readers done

        // issue next two tiles into the slots consumed LAST iteration
        if (kt0 + 2 < NT) {
            FL_ISSUE(kt0 + 2);
            FL_ISSUE(kt0 + 3);
        }

#pragma unroll
        for (int sub = 0; sub < 2; sub++) {
            const __half* Ks = smf + ((kt0 + sub) & 3) * STG;
            const __half* Vs = Ks + 64 * LDS;

            // S' = Q' K^T in fp16 accumulators (log2-domain, pre-scaled).
            unsigned sah[2][8][2];
#pragma unroll
            for (int kd = 0; kd < 4; kd++) {
#pragma unroll
                for (int nb2 = 0; nb2 < 4; nb2++) {
                    unsigned bk[4];
                    ldm_x4(bk, &Ks[(nb2 * 16 + krow_sel) * LDS + kd * 16 + kcol_sel]);
#pragma unroll
                    for (int mi = 0; mi < 2; mi++) {
                        if (kd == 0) {
                            mma_f16c16_z(sah[mi][2 * nb2],     qf[mi][kd], bk[0], bk[1]);
                            mma_f16c16_z(sah[mi][2 * nb2 + 1], qf[mi][kd], bk[2], bk[3]);
                        } else {
                            mma_f16c16(sah[mi][2 * nb2],     qf[mi][kd], bk[0], bk[1]);
                            mma_f16c16(sah[mi][2 * nb2 + 1], qf[mi][kd], bk[2], bk[3]);
                        }
                    }
                }
            }

            // P = 2^S' IN PLACE: the f16 D-fragment IS the PV A-fragment layout.
#pragma unroll
            for (int mi = 0; mi < 2; mi++)
#pragma unroll
                for (int nb = 0; nb < 8; nb++) {
                    sah[mi][nb][0] = ex2_h2(sah[mi][nb][0]);
                    sah[mi][nb][1] = ex2_h2(sah[mi][nb][1]);
                }

            // O += P V  (fp32 accumulators, tensor pipe)
#pragma unroll
            for (int kk = 0; kk < 4; kk++) {
                unsigned aP[2][4];
#pragma unroll
                for (int mi = 0; mi < 2; mi++) {
                    aP[mi][0] = sah[mi][2 * kk][0];
                    aP[mi][1] = sah[mi][2 * kk][1];
                    aP[mi][2] = sah[mi][2 * kk + 1][0];
                    aP[mi][3] = sah[mi][2 * kk + 1][1];
                }
#pragma unroll
                for (int db2 = 0; db2 < 4; db2++) {
                    unsigned bv[4];
                    ldm_x4_t(bv, &Vs[(kk * 16 + vrow_sel) * LDS + db2 * 16 + vcol_sel]);
#pragma unroll
                    for (int mi = 0; mi < 2; mi++) {
                        mma_f16(fo[mi][2 * db2],     aP[mi], bv[0], bv[1]);
                        mma_f16(fo[mi][2 * db2 + 1], aP[mi], bv[2], bv[3]);
                    }
                }
            }

            // rowsum: hadd2 tree over the 4 k-chunks then ONE ONES-mma per mi.
#pragma unroll
            for (int mi = 0; mi < 2; mi++) {
                unsigned ps[4];
                ps[0] = hadd2(hadd2(sah[mi][0][0], sah[mi][2][0]),
                              hadd2(sah[mi][4][0], sah[mi][6][0]));
                ps[1] = hadd2(hadd2(sah[mi][0][1], sah[mi][2][1]),
                              hadd2(sah[mi][4][1], sah[mi][6][1]));
                ps[2] = hadd2(hadd2(sah[mi][1][0], sah[mi][3][0]),
                              hadd2(sah[mi][5][0], sah[mi][7][0]));
                ps[3] = hadd2(hadd2(sah[mi][1][1], sah[mi][3][1]),
                              hadd2(sah[mi][5][1], sah[mi][7][1]));
                mma_f16(lsum[mi], ps, ONES, ONES);
            }
        }
    }
#undef FL_ISSUE

    // epilogue: O /= rowsum (mma already reduced over k; no shuffles needed)
    int b = bh / H_, h = bh - b * H_;
#pragma unroll
    for (int mi = 0; mi < 2; mi++) {
        float inv0 = 1.0f / lsum[mi][0];
        float inv1 = 1.0f / lsum[mi][2];
        int row0 = qb * 128 + warp * 32 + mi * 16 + g;
        __half* O0 = g_oh + ((size_t)(b * S_) + row0) * D_ + h * DK;
        __half* O1 = O0 + 8 * D_;
#pragma unroll
        for (int db = 0; db < 8; db++) {
            int c = db * 8 + 2 * tig;
            *(unsigned*)(O0 + c) = pack_f16(fo[mi][db][0] * inv0, fo[mi][db][1] * inv0);
            *(unsigned*)(O1 + c) = pack_f16(fo[mi][db][2] * inv1, fo[mi][db][3] * inv1);
        }
    }
}

// ---------------- host launcher ------------------------------------------------
extern "C" void kernel_launch(void* const* d_in, const int* in_sizes, int n_in,
                              void* d_out, int out_size)
{
    (void)in_sizes; (void)n_in; (void)out_size;
    const float* x   = (const float*)d_in[0];
    const float* a0  = (const float*)d_in[1];
    const float* b0  = (const float*)d_in[2];
    const float* ra0 = (const float*)d_in[3];
    const float* rb0 = (const float*)d_in[4];
    const float* ra1 = (const float*)d_in[5];
    const float* rb1 = (const float*)d_in[6];
    const float* wq  = (const float*)d_in[7];
    const float* bq  = (const float*)d_in[8];
    const float* wk  = (const float*)d_in[9];
    const float* bk  = (const float*)d_in[10];
    const float* wv  = (const float*)d_in[11];
    const float* bv  = (const float*)d_in[12];
    const float* wo  = (const float*)d_in[13];
    const float* bo  = (const float*)d_in[14];
    float* out = (float*)d_out;

    cudaFuncSetAttribute(flash_mma_kernel,
                         cudaFuncAttributeMaxDynamicSharedMemorySize,
                         FL4_SMEM_BYTES);
    cudaFuncSetAttribute(mma_qkv_kernel,
                         cudaFuncAttributeMaxDynamicSharedMemorySize,
                         PROJ_SMEM_BYTES);
    cudaFuncSetAttribute(mma_out_kernel,
                         cudaFuncAttributeMaxDynamicSharedMemorySize,
                         PROJ_SMEM_BYTES);

    dim3 gQKV(R_ / 128, 18);
    dim3 gOUT(R_ / 128, 6);
    dim3 gFLA(S_ / 128, B_ * H_);

    convw_kernel<<<dim3(144, 4), 256>>>(wq, wk, wv, wo);

    // ---- block 1 ----
    ln2_kernel<<<R_, 128>>>(x, ra0, rb0, a0, b0);
    mma_qkv_kernel<<<gQKV, 256, PROJ_SMEM_BYTES>>>(bq, bk, bv);
    flash_mma_kernel<<<gFLA, 128, FL4_SMEM_BYTES>>>();
    mma_out_kernel<<<gOUT, 256, PROJ_SMEM_BYTES>>>(bo, x, out);

    // ---- block 2 ----
    ln2_kernel<<<R_, 128>>>(out, ra1, rb1, a0, b0);
    mma_qkv_kernel<<<gQKV, 256, PROJ_SMEM_BYTES>>>(bq, bk, bv);
    flash_mma_kernel<<<gFLA, 128, FL4_SMEM_BYTES>>>();
    mma_out_kernel<<<gOUT, 256, PROJ_SMEM_BYTES>>>(bo, out, out);
}

// round 17
// speedup vs baseline: 1.0646x; 1.0646x over previous
#include <cuda_runtime.h>
#include <cuda_fp16.h>
#include <math.h>

#define B_  2
#define S_  4096
#define D_  384
#define H_  6
#define DK  64
#define R_  (B_*S_)
#define EPS 1e-6f
#define LDS 72    // smem row stride (fp16 elems): 144B rows -> conflict-free ldmatrix
#define NT  (S_/64)

// ---------------- scratch (device globals; no allocation allowed) ----------
__device__ __half g_zh[R_ * D_];                 // double-LN output (fp16)
__device__ __half g_q[B_ * H_ * S_ * DK];        // pre-scaled by 0.125*log2(e)
__device__ __half g_k[B_ * H_ * S_ * DK];
__device__ __half g_v[B_ * H_ * S_ * DK];
__device__ __half g_oh[R_ * D_];                 // attention output (fp16)
__device__ __half g_wh[4 * D_ * D_];             // wq|wk|wv|wo in fp16

// ---------------- mma / ldmatrix helpers ------------------------------------
__device__ __forceinline__ unsigned smem_u32(const void* p) {
    return (unsigned)__cvta_generic_to_shared(p);
}
__device__ __forceinline__ void ldm_x4(unsigned r[4], const void* p) {
    unsigned a = smem_u32(p);
    asm volatile("ldmatrix.sync.aligned.m8n8.x4.shared.b16 {%0,%1,%2,%3}, [%4];"
                 : "=r"(r[0]), "=r"(r[1]), "=r"(r[2]), "=r"(r[3]) : "r"(a));
}
__device__ __forceinline__ void ldm_x4_t(unsigned r[4], const void* p) {
    unsigned a = smem_u32(p);
    asm volatile("ldmatrix.sync.aligned.m8n8.x4.trans.shared.b16 {%0,%1,%2,%3}, [%4];"
                 : "=r"(r[0]), "=r"(r[1]), "=r"(r[2]), "=r"(r[3]) : "r"(a));
}
// fp32-accumulator mma
__device__ __forceinline__ void mma_f16(float c[4], const unsigned a[4],
                                        unsigned b0, unsigned b1) {
    asm volatile("mma.sync.aligned.m16n8k16.row.col.f32.f16.f16.f32 "
                 "{%0,%1,%2,%3}, {%4,%5,%6,%7}, {%8,%9}, {%0,%1,%2,%3};"
                 : "+f"(c[0]), "+f"(c[1]), "+f"(c[2]), "+f"(c[3])
                 : "r"(a[0]), "r"(a[1]), "r"(a[2]), "r"(a[3]), "r"(b0), "r"(b1));
}
// fp16-accumulator mma (accumulating form)
__device__ __forceinline__ void mma_f16c16(unsigned c[2], const unsigned a[4],
                                           unsigned b0, unsigned b1) {
    asm volatile("mma.sync.aligned.m16n8k16.row.col.f16.f16.f16.f16 "
                 "{%0,%1}, {%2,%3,%4,%5}, {%6,%7}, {%0,%1};"
                 : "+r"(c[0]), "+r"(c[1])
                 : "r"(a[0]), "r"(a[1]), "r"(a[2]), "r"(a[3]), "r"(b0), "r"(b1));
}
// fp16-accumulator mma, zero-initializing (C = 0)
__device__ __forceinline__ void mma_f16c16_z(unsigned c[2], const unsigned a[4],
                                             unsigned b0, unsigned b1) {
    asm volatile("mma.sync.aligned.m16n8k16.row.col.f16.f16.f16.f16 "
                 "{%0,%1}, {%2,%3,%4,%5}, {%6,%7}, {%8,%8};"
                 : "=r"(c[0]), "=r"(c[1])
                 : "r"(a[0]), "r"(a[1]), "r"(a[2]), "r"(a[3]), "r"(b0), "r"(b1),
                   "r"(0u));
}
// pack two f32 into f16x2: low half = lo, high half = hi
__device__ __forceinline__ unsigned pack_f16(float lo, float hi) {
    unsigned d;
    asm("cvt.rn.f16x2.f32 %0, %1, %2;" : "=r"(d) : "f"(hi), "f"(lo));
    return d;
}
// two exponentials (base 2) in one op; in-place on an fp16x2 fragment reg
__device__ __forceinline__ unsigned ex2_h2(unsigned x) {
    unsigned r;
    asm("ex2.approx.f16x2 %0, %1;" : "=r"(r) : "r"(x));
    return r;
}
__device__ __forceinline__ unsigned hadd2(unsigned a, unsigned b) {
    unsigned d;
    asm("add.f16x2 %0, %1, %2;" : "=r"(d) : "r"(a), "r"(b));
    return d;
}
__device__ __forceinline__ void cp_async16(void* dst, const void* src) {
    unsigned d = smem_u32(dst);
    asm volatile("cp.async.cg.shared.global [%0], [%1], 16;" :: "r"(d), "l"(src));
}
#define CP_COMMIT() asm volatile("cp.async.commit_group;" ::: "memory")
#define CP_WAIT1()  asm volatile("cp.async.wait_group 1;" ::: "memory")

// ---------------- weight conversion ------------------------------------------
__global__ __launch_bounds__(256) void convw_kernel(
    const float* __restrict__ wq, const float* __restrict__ wk,
    const float* __restrict__ wv, const float* __restrict__ wo)
{
    const float* src = (blockIdx.y == 0) ? wq : (blockIdx.y == 1) ? wk
                     : (blockIdx.y == 2) ? wv : wo;
    __half* dst = g_wh + (size_t)blockIdx.y * D_ * D_;
    int i = (blockIdx.x * 256 + threadIdx.x) * 4;
    float4 v = *(const float4*)(src + i);
    *(unsigned*)(dst + i)     = pack_f16(v.x, v.y);
    *(unsigned*)(dst + i + 2) = pack_f16(v.z, v.w);
}

// ---------------- fused double LayerNorm: WARP-PER-ROW ------------------------
// 256 threads = 8 warps = 8 rows per block; grid R_/8 = 1024... (R_=8192 -> 1024
// blocks). All reductions are 5-level shfl_xor within the warp: ZERO barriers,
// zero smem. Each lane owns 12 floats (3 float4), coalesced across the warp.
__global__ __launch_bounds__(256) void ln2_kernel(
    const float* __restrict__ x,
    const float* __restrict__ ra, const float* __restrict__ rb,
    const float* __restrict__ a0, const float* __restrict__ b0)
{
    int warp = threadIdx.x >> 5, lane = threadIdx.x & 31;
    int row = blockIdx.x * 8 + warp;
    const float4* xr = (const float4*)(x + (size_t)row * D_);

    float4 v4[3];
    float v[12];
#pragma unroll
    for (int c = 0; c < 3; c++) {
        v4[c] = xr[lane + 32 * c];
        v[4 * c]     = v4[c].x;
        v[4 * c + 1] = v4[c].y;
        v[4 * c + 2] = v4[c].z;
        v[4 * c + 3] = v4[c].w;
    }

    // ---- LN 1 ----
    float s = 0.f;
#pragma unroll
    for (int i = 0; i < 12; i++) s += v[i];
#pragma unroll
    for (int o = 16; o > 0; o >>= 1) s += __shfl_xor_sync(0xffffffffu, s, o);
    float mean = s * (1.0f / D_);
    float sq = 0.f;
#pragma unroll
    for (int i = 0; i < 12; i++) { float d = v[i] - mean; sq += d * d; }
#pragma unroll
    for (int o = 16; o > 0; o >>= 1) sq += __shfl_xor_sync(0xffffffffu, sq, o);
    float inv = 1.0f / (sqrtf(sq * (1.0f / (D_ - 1))) + EPS);

    float y[12];
#pragma unroll
    for (int c = 0; c < 3; c++)
#pragma unroll
        for (int k = 0; k < 4; k++) {
            int i = (lane + 32 * c) * 4 + k;
            y[4 * c + k] = ra[i] * (v[4 * c + k] - mean) * inv + rb[i];
        }

    // ---- LN 2 ----
    s = 0.f;
#pragma unroll
    for (int i = 0; i < 12; i++) s += y[i];
#pragma unroll
    for (int o = 16; o > 0; o >>= 1) s += __shfl_xor_sync(0xffffffffu, s, o);
    mean = s * (1.0f / D_);
    sq = 0.f;
#pragma unroll
    for (int i = 0; i < 12; i++) { float d = y[i] - mean; sq += d * d; }
#pragma unroll
    for (int o = 16; o > 0; o >>= 1) sq += __shfl_xor_sync(0xffffffffu, sq, o);
    inv = 1.0f / (sqrtf(sq * (1.0f / (D_ - 1))) + EPS);

    __half* zr = g_zh + (size_t)row * D_;
#pragma unroll
    for (int c = 0; c < 3; c++) {
        int i0 = (lane + 32 * c) * 4;
        float z0 = a0[i0]     * (y[4 * c]     - mean) * inv + b0[i0];
        float z1 = a0[i0 + 1] * (y[4 * c + 1] - mean) * inv + b0[i0 + 1];
        float z2 = a0[i0 + 2] * (y[4 * c + 2] - mean) * inv + b0[i0 + 2];
        float z3 = a0[i0 + 3] * (y[4 * c + 3] - mean) * inv + b0[i0 + 3];
        uint2 p;
        p.x = pack_f16(z0, z1);
        p.y = pack_f16(z2, z3);
        *(uint2*)(zr + i0) = p;
    }
}

// ---------------- projection kernels: cp.async 3-stage ring --------------------
#define PST ((128 + 64) * LDS)            // halfs per stage
#define PROJ_SMEM_BYTES (PST * 3 * 2)     // 82944 bytes -> 2 CTAs/SM, 16 warps

// ---------------- QKV projection (fp16 tensor mma) ----------------------------
// grid (R_/128, 18), 256 threads. Tile 128M x 64N, BK=64.
__global__ __launch_bounds__(256) void mma_qkv_kernel(
    const float* __restrict__ bq, const float* __restrict__ bk,
    const float* __restrict__ bv)
{
    extern __shared__ __half smp[];

    int tid = threadIdx.x, warp = tid >> 5, lane = tid & 31;
    int g = lane >> 2, tig = lane & 3;
    int m0 = blockIdx.x * 128;
    int ntile = blockIdx.y;              // 0..17
    int which = ntile / 6;
    int h = ntile - which * 6;
    const __half* W = g_wh + (size_t)which * (D_ * D_) + (size_t)h * 64 * D_;
    const float* bias = ((which == 0) ? bq : (which == 1) ? bk : bv) + h * 64;
    __half* Out = (which == 0) ? g_q : (which == 1) ? g_k : g_v;

    int r8 = tid >> 3, c8 = tid & 7;

#define QKV_ISSUE(kc) do {                                                      \
        __half* SA_ = smp + ((kc) % 3) * PST;                                   \
        __half* SB_ = SA_ + 128 * LDS;                                          \
        int k0_ = (kc) * 64;                                                    \
        _Pragma("unroll")                                                       \
        for (int j = 0; j < 4; j++) {                                           \
            int r = r8 + j * 32;                                                \
            cp_async16(&SA_[r * LDS + c8 * 8],                                  \
                       g_zh + (size_t)(m0 + r) * D_ + k0_ + c8 * 8);            \
        }                                                                       \
        _Pragma("unroll")                                                       \
        for (int j = 0; j < 2; j++) {                                           \
            int r = r8 + j * 32;                                                \
            cp_async16(&SB_[r * LDS + c8 * 8],                                  \
                       W + (size_t)r * D_ + k0_ + c8 * 8);                      \
        }                                                                       \
        CP_COMMIT();                                                            \
    } while (0)

    QKV_ISSUE(0);
    QKV_ISSUE(1);

    float acc[2][4][4] = {};
    int arow_sel = ((lane & 8) ? 8 : 0) + (lane & 7);
    int acol_sel = ((lane & 16) ? 8 : 0);
    int brow_sel = ((lane & 16) ? 8 : 0) + (lane & 7);
    int bcol_sel = ((lane & 8) ? 8 : 0);
    int mbase = (warp >> 1) * 32;
    int nbase = (warp & 1) * 32;

    for (int kc = 0; kc < 6; kc++) {
        CP_WAIT1();
        __syncthreads();           // chunk kc landed for ALL threads; slot (kc+2)%3 free
        if (kc + 2 < 6) QKV_ISSUE(kc + 2); else CP_COMMIT();

        const __half* SA = smp + (kc % 3) * PST;
        const __half* SB = SA + 128 * LDS;
#pragma unroll
        for (int ks = 0; ks < 4; ks++) {
            unsigned af[2][4], bf0[4], bf1[4];
            ldm_x4(af[0], &SA[(mbase + arow_sel) * LDS + ks * 16 + acol_sel]);
            ldm_x4(af[1], &SA[(mbase + 16 + arow_sel) * LDS + ks * 16 + acol_sel]);
            ldm_x4(bf0, &SB[(nbase + brow_sel) * LDS + ks * 16 + bcol_sel]);
            ldm_x4(bf1, &SB[(nbase + 16 + brow_sel) * LDS + ks * 16 + bcol_sel]);
#pragma unroll
            for (int mi = 0; mi < 2; mi++) {
                mma_f16(acc[mi][0], af[mi], bf0[0], bf0[1]);
                mma_f16(acc[mi][1], af[mi], bf0[2], bf0[3]);
                mma_f16(acc[mi][2], af[mi], bf1[0], bf1[1]);
                mma_f16(acc[mi][3], af[mi], bf1[2], bf1[3]);
            }
        }
    }
#undef QKV_ISSUE

    // fold 1/sqrt(dk) AND log2(e) into q so flash can use raw ex2
    float qs = (which == 0) ? 0.125f * 1.44269504f : 1.0f;
#pragma unroll
    for (int nb = 0; nb < 4; nb++) {
        int j = nbase + nb * 8 + 2 * tig;
        float b0v = bias[j], b1v = bias[j + 1];
#pragma unroll
        for (int mi = 0; mi < 2; mi++) {
            int row = m0 + mbase + mi * 16 + g;
            int bidx = row >> 12;
            int s = row & (S_ - 1);
            __half* po = Out + (((size_t)(bidx * H_ + h)) * S_ + s) * DK + j;
            *(unsigned*)po            = pack_f16((acc[mi][nb][0] + b0v) * qs,
                                                 (acc[mi][nb][1] + b1v) * qs);
            *(unsigned*)(po + 8 * DK) = pack_f16((acc[mi][nb][2] + b0v) * qs,
                                                 (acc[mi][nb][3] + b1v) * qs);
        }
    }
}

// ---------------- output projection + residual (fp16 mma, fp32 out) -----------
__global__ __launch_bounds__(256) void mma_out_kernel(
    const float* __restrict__ bo, const float* __restrict__ xres,
    float* __restrict__ out)
{
    extern __shared__ __half smp[];

    int tid = threadIdx.x, warp = tid >> 5, lane = tid & 31;
    int g = lane >> 2, tig = lane & 3;
    int m0 = blockIdx.x * 128;
    int n0 = blockIdx.y * 64;
    const __half* W = g_wh + (size_t)3 * D_ * D_ + (size_t)n0 * D_;

    int r8 = tid >> 3, c8 = tid & 7;

#define OUT_ISSUE(kc) do {                                                      \
        __half* SA_ = smp + ((kc) % 3) * PST;                                   \
        __half* SB_ = SA_ + 128 * LDS;                                          \
        int k0_ = (kc) * 64;                                                    \
        _Pragma("unroll")                                                       \
        for (int j = 0; j < 4; j++) {                                           \
            int r = r8 + j * 32;                                                \
            cp_async16(&SA_[r * LDS + c8 * 8],                                  \
                       g_oh + (size_t)(m0 + r) * D_ + k0_ + c8 * 8);            \
        }                                                                       \
        _Pragma("unroll")                                                       \
        for (int j = 0; j < 2; j++) {                                           \
            int r = r8 + j * 32;                                                \
            cp_async16(&SB_[r * LDS + c8 * 8],                                  \
                       W + (size_t)r * D_ + k0_ + c8 * 8);                      \
        }                                                                       \
        CP_COMMIT();                                                            \
    } while (0)

    OUT_ISSUE(0);
    OUT_ISSUE(1);

    float acc[2][4][4] = {};
    int arow_sel = ((lane & 8) ? 8 : 0) + (lane & 7);
    int acol_sel = ((lane & 16) ? 8 : 0);
    int brow_sel = ((lane & 16) ? 8 : 0) + (lane & 7);
    int bcol_sel = ((lane & 8) ? 8 : 0);
    int mbase = (warp >> 1) * 32;
    int nbase = (warp & 1) * 32;

    for (int kc = 0; kc < 6; kc++) {
        CP_WAIT1();
        __syncthreads();
        if (kc + 2 < 6) OUT_ISSUE(kc + 2); else CP_COMMIT();

        const __half* SA = smp + (kc % 3) * PST;
        const __half* SB = SA + 128 * LDS;
#pragma unroll
        for (int ks = 0; ks < 4; ks++) {
            unsigned af[2][4], bf0[4], bf1[4];
            ldm_x4(af[0], &SA[(mbase + arow_sel) * LDS + ks * 16 + acol_sel]);
            ldm_x4(af[1], &SA[(mbase + 16 + arow_sel) * LDS + ks * 16 + acol_sel]);
            ldm_x4(bf0, &SB[(nbase + brow_sel) * LDS + ks * 16 + bcol_sel]);
            ldm_x4(bf1, &SB[(nbase + 16 + brow_sel) * LDS + ks * 16 + bcol_sel]);
#pragma unroll
            for (int mi = 0; mi < 2; mi++) {
                mma_f16(acc[mi][0], af[mi], bf0[0], bf0[1]);
                mma_f16(acc[mi][1], af[mi], bf0[2], bf0[3]);
                mma_f16(acc[mi][2], af[mi], bf1[0], bf1[1]);
                mma_f16(acc[mi][3], af[mi], bf1[2], bf1[3]);
            }
        }
    }
#undef OUT_ISSUE

#pragma unroll
    for (int nb = 0; nb < 4; nb++) {
        int col = n0 + nbase + nb * 8 + 2 * tig;
        float b0v = bo[col], b1v = bo[col + 1];
#pragma unroll
        for (int mi = 0; mi < 2; mi++) {
            int row = m0 + mbase + mi * 16 + g;
            float2 x0 = *(const float2*)(xres + (size_t)row * D_ + col);
            float2 x1 = *(const float2*)(xres + (size_t)(row + 8) * D_ + col);
            float2 o0, o1;
            o0.x = x0.x + acc[mi][nb][0] + b0v;
            o0.y = x0.y + acc[mi][nb][1] + b1v;
            o1.x = x1.x + acc[mi][nb][2] + b0v;
            o1.y = x1.y + acc[mi][nb][3] + b1v;
            *(float2*)(out + (size_t)row * D_ + col)       = o0;
            *(float2*)(out + (size_t)(row + 8) * D_ + col) = o1;
        }
    }
}

// ---------------- flash attention (fp16 mma, fixed-base softmax) ---------------
// EXACT R15 version (measured best: 135.3us/call): 3 CTAs/SM, fp16 S-acc,
// in-place ex2, hadd2-fused single ONES-mma denominator, cp.async 3-stage
// ring with CP_WAIT1 + one barrier per tile.
#define FL3_SMEM_BYTES ((128 * LDS + 6 * 64 * LDS) * 2)

__global__ __launch_bounds__(128, 3) void flash_mma_kernel()
{
    extern __shared__ __half smf[];
    __half* Qs = smf;                         // 128 rows

    int tid = threadIdx.x, warp = tid >> 5, lane = tid & 31;
    int g = lane >> 2, tig = lane & 3;
    int bh = blockIdx.y, qb = blockIdx.x;

    const __half* Qg = g_q + ((size_t)bh * S_ + qb * 128) * DK;
    const __half* Kg = g_k + (size_t)bh * S_ * DK;
    const __half* Vg = g_v + (size_t)bh * S_ * DK;

    // cp.async prefetch stages 0 and 1 of the K/V ring
    int krow = tid >> 3, kchk = tid & 7;     // krow 0..15
#pragma unroll
    for (int st = 0; st < 2; st++) {
        __half* Kd = smf + (128 + st * 128) * LDS;
        __half* Vd = Kd + 64 * LDS;
        const __half* Kt = Kg + (size_t)st * 64 * DK;
        const __half* Vt = Vg + (size_t)st * 64 * DK;
#pragma unroll
        for (int j = 0; j < 4; j++) {
            int r = krow + j * 16;
            cp_async16(&Kd[r * LDS + kchk * 8], Kt + r * DK + kchk * 8);
            cp_async16(&Vd[r * LDS + kchk * 8], Vt + r * DK + kchk * 8);
        }
        CP_COMMIT();
    }

    // Q tile -> smem (plain loads), then register fragments
#pragma unroll
    for (int j = 0; j < 8; j++) {
        int i = tid + j * 128;
        int r = i >> 3, c = i & 7;
        *(uint4*)&Qs[r * LDS + c * 8] = *(const uint4*)(Qg + r * DK + c * 8);
    }
    __syncthreads();

    unsigned qf[2][4][4];
    {
        int rsel = ((lane & 8) ? 8 : 0) + (lane & 7);
        int csel = ((lane & 16) ? 8 : 0);
#pragma unroll
        for (int mi = 0; mi < 2; mi++)
#pragma unroll
            for (int kd = 0; kd < 4; kd++)
                ldm_x4(qf[mi][kd], &Qs[(warp * 32 + mi * 16 + rsel) * LDS + kd * 16 + csel]);
    }

    float fo[2][8][4] = {};
    float lsum[2][4] = {};
    const unsigned ONES = 0x3C003C00u;   // fp16x2 {1.0, 1.0}

    int krow_sel = ((lane & 16) ? 8 : 0) + (lane & 7);   // B-frag (K, non-trans)
    int kcol_sel = ((lane & 8) ? 8 : 0);
    int vrow_sel = ((lane & 8) ? 8 : 0) + (lane & 7);    // B-frag (V, trans)
    int vcol_sel = ((lane & 16) ? 8 : 0);

    for (int kt = 0; kt < NT; kt++) {
        CP_WAIT1();                 // stage kt landed (kt+1 may be in flight)
        __syncthreads();            // all threads' copies visible; prior readers done

        // issue prefetch for stage kt+2 into ring slot (kt+2)%3
        if (kt + 2 < NT) {
            int st = (kt + 2) % 3;
            __half* Kd = smf + (128 + st * 128) * LDS;
            __half* Vd = Kd + 64 * LDS;
            const __half* Kt = Kg + (size_t)(kt + 2) * 64 * DK;
            const __half* Vt = Vg + (size_t)(kt + 2) * 64 * DK;
#pragma unroll
            for (int j = 0; j < 4; j++) {
                int r = krow + j * 16;
                cp_async16(&Kd[r * LDS + kchk * 8], Kt + r * DK + kchk * 8);
                cp_async16(&Vd[r * LDS + kchk * 8], Vt + r * DK + kchk * 8);
            }
        }
        CP_COMMIT();                // commit (possibly empty) to keep group count

        const __half* Ks = smf + (128 + (kt % 3) * 128) * LDS;
        const __half* Vs = Ks + 64 * LDS;

        // S' = Q' K^T in fp16 accumulators (log2-domain, pre-scaled).
        unsigned sah[2][8][2];
#pragma unroll
        for (int kd = 0; kd < 4; kd++) {
#pragma unroll
            for (int nb2 = 0; nb2 < 4; nb2++) {
                unsigned bk[4];
                ldm_x4(bk, &Ks[(nb2 * 16 + krow_sel) * LDS + kd * 16 + kcol_sel]);
#pragma unroll
                for (int mi = 0; mi < 2; mi++) {
                    if (kd == 0) {
                        mma_f16c16_z(sah[mi][2 * nb2],     qf[mi][kd], bk[0], bk[1]);
                        mma_f16c16_z(sah[mi][2 * nb2 + 1], qf[mi][kd], bk[2], bk[3]);
                    } else {
                        mma_f16c16(sah[mi][2 * nb2],     qf[mi][kd], bk[0], bk[1]);
                        mma_f16c16(sah[mi][2 * nb2 + 1], qf[mi][kd], bk[2], bk[3]);
                    }
                }
            }
        }

        // P = 2^S' IN PLACE: the f16 D-fragment IS the PV A-fragment layout.
#pragma unroll
        for (int mi = 0; mi < 2; mi++)
#pragma unroll
            for (int nb = 0; nb < 8; nb++) {
                sah[mi][nb][0] = ex2_h2(sah[mi][nb][0]);
                sah[mi][nb][1] = ex2_h2(sah[mi][nb][1]);
            }

        // O += P V  (fp32 accumulators, tensor pipe)
#pragma unroll
        for (int kk = 0; kk < 4; kk++) {
            unsigned aP[2][4];
#pragma unroll
            for (int mi = 0; mi < 2; mi++) {
                aP[mi][0] = sah[mi][2 * kk][0];
                aP[mi][1] = sah[mi][2 * kk][1];
                aP[mi][2] = sah[mi][2 * kk + 1][0];
                aP[mi][3] = sah[mi][2 * kk + 1][1];
            }
#pragma unroll
            for (int db2 = 0; db2 < 4; db2++) {
                unsigned bv[4];
                ldm_x4_t(bv, &Vs[(kk * 16 + vrow_sel) * LDS + db2 * 16 + vcol_sel]);
#pragma unroll
                for (int mi = 0; mi < 2; mi++) {
                    mma_f16(fo[mi][2 * db2],     aP[mi], bv[0], bv[1]);
                    mma_f16(fo[mi][2 * db2 + 1], aP[mi], bv[2], bv[3]);
                }
            }
        }

        // rowsum: pre-sum P A-fragments over the 4 k-chunks (hadd2 tree on the
        // alu pipe; mma is linear in A) then ONE ONES-mma per mi.
#pragma unroll
        for (int mi = 0; mi < 2; mi++) {
            unsigned ps[4];
            ps[0] = hadd2(hadd2(sah[mi][0][0], sah[mi][2][0]),
                          hadd2(sah[mi][4][0], sah[mi][6][0]));
            ps[1] = hadd2(hadd2(sah[mi][0][1], sah[mi][2][1]),
                          hadd2(sah[mi][4][1], sah[mi][6][1]));
            ps[2] = hadd2(hadd2(sah[mi][1][0], sah[mi][3][0]),
                          hadd2(sah[mi][5][0], sah[mi][7][0]));
            ps[3] = hadd2(hadd2(sah[mi][1][1], sah[mi][3][1]),
                          hadd2(sah[mi][5][1], sah[mi][7][1]));
            mma_f16(lsum[mi], ps, ONES, ONES);
        }
    }

    // epilogue: O /= rowsum (mma already reduced over k; no shuffles needed)
    int b = bh / H_, h = bh - b * H_;
#pragma unroll
    for (int mi = 0; mi < 2; mi++) {
        float inv0 = 1.0f / lsum[mi][0];
        float inv1 = 1.0f / lsum[mi][2];
        int row0 = qb * 128 + warp * 32 + mi * 16 + g;
        __half* O0 = g_oh + ((size_t)(b * S_) + row0) * D_ + h * DK;
        __half* O1 = O0 + 8 * D_;
#pragma unroll
        for (int db = 0; db < 8; db++) {
            int c = db * 8 + 2 * tig;
            *(unsigned*)(O0 + c) = pack_f16(fo[mi][db][0] * inv0, fo[mi][db][1] * inv0);
            *(unsigned*)(O1 + c) = pack_f16(fo[mi][db][2] * inv1, fo[mi][db][3] * inv1);
        }
    }
}

// ---------------- host launcher ------------------------------------------------
extern "C" void kernel_launch(void* const* d_in, const int* in_sizes, int n_in,
                              void* d_out, int out_size)
{
    (void)in_sizes; (void)n_in; (void)out_size;
    const float* x   = (const float*)d_in[0];
    const float* a0  = (const float*)d_in[1];
    const float* b0  = (const float*)d_in[2];
    const float* ra0 = (const float*)d_in[3];
    const float* rb0 = (const float*)d_in[4];
    const float* ra1 = (const float*)d_in[5];
    const float* rb1 = (const float*)d_in[6];
    const float* wq  = (const float*)d_in[7];
    const float* bq  = (const float*)d_in[8];
    const float* wk  = (const float*)d_in[9];
    const float* bk  = (const float*)d_in[10];
    const float* wv  = (const float*)d_in[11];
    const float* bv  = (const float*)d_in[12];
    const float* wo  = (const float*)d_in[13];
    const float* bo  = (const float*)d_in[14];
    float* out = (float*)d_out;

    cudaFuncSetAttribute(flash_mma_kernel,
                         cudaFuncAttributeMaxDynamicSharedMemorySize,
                         FL3_SMEM_BYTES);
    cudaFuncSetAttribute(mma_qkv_kernel,
                         cudaFuncAttributeMaxDynamicSharedMemorySize,
                         PROJ_SMEM_BYTES);
    cudaFuncSetAttribute(mma_out_kernel,
                         cudaFuncAttributeMaxDynamicSharedMemorySize,
                         PROJ_SMEM_BYTES);

    dim3 gQKV(R_ / 128, 18);
    dim3 gOUT(R_ / 128, 6);
    dim3 gFLA(S_ / 128, B_ * H_);

    convw_kernel<<<dim3(144, 4), 256>>>(wq, wk, wv, wo);

    // ---- block 1 ----
    ln2_kernel<<<R_ / 8, 256>>>(x, ra0, rb0, a0, b0);
    mma_qkv_kernel<<<gQKV, 256, PROJ_SMEM_BYTES>>>(bq, bk, bv);
    flash_mma_kernel<<<gFLA, 128, FL3_SMEM_BYTES>>>();
    mma_out_kernel<<<gOUT, 256, PROJ_SMEM_BYTES>>>(bo, x, out);

    // ---- block 2 ----
    ln2_kernel<<<R_ / 8, 256>>>(out, ra1, rb1, a0, b0);
    mma_qkv_kernel<<<gQKV, 256, PROJ_SMEM_BYTES>>>(bq, bk, bv);
    flash_mma_kernel<<<gFLA, 128, FL3_SMEM_BYTES>>>();
    mma_out_kernel<<<gOUT, 256, PROJ_SMEM_BYTES>>>(bo, out, out);
}